// round 16
// baseline (speedup 1.0000x reference)
#include <cuda_runtime.h>
#include <cuda_fp16.h>

#define B_   256
#define TP_  512
#define TQ_  64
#define DPQ_ 300
#define KP_  320     // padded K for 300-dim GEMMs
#define H_   256
#define G4_  1024

// smem layout (floats) for persist kernel
// P3: ring 4x2304 | W1 (Whh 64x260) @9216 | W2 (Wq 64x324) @25856 | sG @46592 (64x68)
// middle: P2 scratch 0..1280 | sWr half2 col-major stride129 @1280 (33024 f)
#define RING_SLOT_ 2304
#define W1_OFF_    9216
#define W2_OFF_    25856
#define SG_OFF_    46592
#define SMEM_FLOATS_ 50944     // 203,776 bytes

// ---------------- device scratch ----------------
__device__ float  d_qproj[B_*TQ_*H_];
__device__ __half2 d_qproj2[B_*TQ_*128];    // half2 pairs (h=2j, 2j+1)
__device__ __half2 d_WrH[128*256];          // Wr half2, k-major: [k2*256 + c] = (Wr[2k2][c], Wr[2k2+1][c])
__device__ float d_pW[TP_*B_*H_];           // time-major [st][b][h]
__device__ float d_ppre[TP_*B_*G4_];        // time-major [st][b][j] (permuted gate cols)
__device__ float d_W2T[1280*H_];            // n-major; rows >=256 = permuted Whh cols (tf32)
__device__ float d_WqT2[G4_*KP_];           // n-major permuted [j][k], k>=300 zero
__device__ float d_WihpT2[G4_*KP_];
__device__ float d_WqTn[H_*KP_];
__device__ float d_WpTn[H_*KP_];
__device__ float d_bias[G4_];
__device__ float d_ctx[B_*KP_];
__device__ float d_h[B_*H_];
__device__ float d_c[B_*H_];
__device__ unsigned g_cnt;
__device__ unsigned g_gen;
__device__ unsigned d_flags[256];

// ---------------- helpers ----------------
__device__ __forceinline__ float tanha(float x){
    float y; asm("tanh.approx.f32 %0, %1;" : "=f"(y) : "f"(x)); return y;
}
__device__ __forceinline__ __half2 tanh2(__half2 x){
    unsigned u = *(unsigned*)&x, r;
    asm("tanh.approx.f16x2 %0, %1;" : "=r"(r) : "r"(u));
    return *(__half2*)&r;
}
__device__ __forceinline__ float sigm2(float x){
    return fmaf(tanha(0.5f*x), 0.5f, 0.5f);
}
__device__ __forceinline__ float to_tf32(float x){
    unsigned u; asm("cvt.rna.tf32.f32 %0, %1;" : "=r"(u) : "f"(x));
    return __uint_as_float(u);
}
__device__ __forceinline__ unsigned long long ffma2_(unsigned long long a,
                                                     unsigned long long b,
                                                     unsigned long long c){
    unsigned long long d;
    asm("fma.rn.f32x2 %0, %1, %2, %3;" : "=l"(d) : "l"(a), "l"(b), "l"(c));
    return d;
}
__device__ __forceinline__ unsigned long long packf2(float lo, float hi){
    unsigned long long u;
    asm("mov.b64 %0, {%1, %2};" : "=l"(u) : "f"(lo), "f"(hi));
    return u;
}
__device__ __forceinline__ float2 unpackf2(unsigned long long u){
    float lo, hi;
    asm("mov.b64 {%0, %1}, %2;" : "=f"(lo), "=f"(hi) : "l"(u));
    return make_float2(lo, hi);
}
__device__ __forceinline__ void mma8(float* d, unsigned a0, unsigned a1, unsigned a2, unsigned a3,
                                     unsigned b0, unsigned b1){
    asm volatile("mma.sync.aligned.m16n8k8.row.col.f32.tf32.tf32.f32 "
                 "{%0,%1,%2,%3},{%4,%5,%6,%7},{%8,%9},{%0,%1,%2,%3};"
                 : "+f"(d[0]), "+f"(d[1]), "+f"(d[2]), "+f"(d[3])
                 : "r"(a0), "r"(a1), "r"(a2), "r"(a3), "r"(b0), "r"(b1));
}
__device__ __forceinline__ void cpa16(unsigned s, const float* g){
    asm volatile("cp.async.cg.shared.global [%0], [%1], 16;" :: "r"(s), "l"(g));
}
#define CP_COMMIT() asm volatile("cp.async.commit_group;" ::: "memory")
#define CP_WAIT2()  asm volatile("cp.async.wait_group 2;"  ::: "memory")
#define CP_WAIT0()  asm volatile("cp.async.wait_group 0;"  ::: "memory")

__device__ __forceinline__ void pref_l2(const float* p){
    asm volatile("prefetch.global.L2 [%0];" :: "l"(p));
}
__device__ __forceinline__ unsigned ldacq(const unsigned* p){
    unsigned v; asm volatile("ld.acquire.gpu.global.u32 %0, [%1];" : "=r"(v) : "l"(p) : "memory");
    return v;
}
__device__ __forceinline__ void wait_ge(int lo, int n, unsigned tok){
    if (threadIdx.x < 32){
        for(;;){
            bool ok = true;
            for (int i = (int)threadIdx.x; i < n; i += 32)
                if (ldacq(&d_flags[lo+i]) < tok) ok = false;
            if (__all_sync(0xffffffffu, ok)) break;
            __nanosleep(40);
        }
    }
    __syncthreads();
}
__device__ __forceinline__ void set_flag(int bid, unsigned tok){
    __syncthreads();
    if (threadIdx.x == 0)
        asm volatile("st.release.gpu.global.u32 [%0], %1;" :: "l"(&d_flags[bid]), "r"(tok) : "memory");
}

// ---------------- grid barrier (post-init only) ----------------
__device__ __forceinline__ void grid_bar(int nctas){
    __syncthreads();
    if (threadIdx.x == 0){
        __threadfence();
        unsigned g = *(volatile unsigned*)&g_gen;
        unsigned prev = atomicAdd(&g_cnt, 1u);
        if (prev == (unsigned)(nctas - 1)){
            atomicExch(&g_cnt, 0u);
            __threadfence();
            atomicAdd(&g_gen, 1u);
        } else {
            while (*(volatile unsigned*)&g_gen == g) { __nanosleep(32); }
        }
        __threadfence();
    }
    __syncthreads();
}

__device__ __forceinline__ int gperm(int j){ return (j & 3)*H_ + (j >> 2); }

// ---------------- K0: weight prep ----------------
__global__ void prep_kernel(const float* __restrict__ Wq, const float* __restrict__ Wp,
                            const float* __restrict__ Wr, const float* __restrict__ Wih,
                            const float* __restrict__ Whh,
                            const float* __restrict__ bih, const float* __restrict__ bhh){
    int idx0 = blockIdx.x*blockDim.x + threadIdx.x;
    int stride = gridDim.x*blockDim.x;
    for (int i = idx0; i < 1280*H_; i += stride){
        int n = i / H_, k = i - n*H_;
        float v = (n < H_) ? Wr[k*H_ + n] : Whh[gperm(n - H_)*H_ + k];
        d_W2T[i] = to_tf32(v);
    }
    for (int i = idx0; i < 128*256; i += stride){
        int k2 = i >> 8, c = i & 255;
        d_WrH[i] = __floats2half2_rn(Wr[(2*k2)*H_ + c], Wr[(2*k2+1)*H_ + c]);
    }
    for (int i = idx0; i < G4_*KP_; i += stride){
        int j = i / KP_, k = i - j*KP_;
        int a = gperm(j);
        d_WqT2[i]   = (k < DPQ_) ? to_tf32(Wih[a*600 + 300 + k]) : 0.f;
        d_WihpT2[i] = (k < DPQ_) ? to_tf32(Wih[a*600 + k])       : 0.f;
    }
    for (int i = idx0; i < H_*KP_; i += stride){
        int n = i / KP_, k = i - n*KP_;
        d_WqTn[i] = (k < DPQ_) ? to_tf32(Wq[k*H_ + n]) : 0.f;
        d_WpTn[i] = (k < DPQ_) ? to_tf32(Wp[k*H_ + n]) : 0.f;
    }
    for (int j = idx0; j < G4_; j += stride){
        int a = gperm(j);
        d_bias[j] = bih[a] + bhh[a];
    }
}

__global__ void reset_kernel(){
    if (blockIdx.x == 0 && threadIdx.x < 256) d_flags[threadIdx.x] = 0u;
}

// ---------------- qproj fp32 -> half2 pairs ----------------
__global__ void qconv_kernel(){
    int i = blockIdx.x*blockDim.x + threadIdx.x;
    if (i < B_*TQ_*128)
        d_qproj2[i] = __floats2half2_rn(d_qproj[2*i], d_qproj[2*i+1]);
}

// ---------------- upfront tf32 GEMM (proven) ----------------
__device__ __forceinline__ void stage_load(const float* __restrict__ Ag, int lda,
                                           const float* __restrict__ Bg, int ldb,
                                           float* sA, float* sB, int tid, int krem){
    #pragma unroll
    for (int i = 0; i < 2; i++){
        int f = tid + i*256;
        int row = f >> 3, c4 = (f & 7)*4;
        float4 va = make_float4(0.f,0.f,0.f,0.f);
        if (c4 < krem) va = *(const float4*)(Ag + (size_t)row*lda + c4);
        *(float4*)(sA + row*36 + c4) = va;
        float4 vb = *(const float4*)(Bg + (size_t)row*ldb + c4);
        *(float4*)(sB + row*36 + c4) = vb;
    }
}
__device__ __forceinline__ void mma_tile_step(const float* sA, const float* sB,
                                              int m0w, int n0w, int g, int tg,
                                              float acc[2][2][4]){
    #pragma unroll
    for (int kk = 0; kk < 32; kk += 8){
        const float* pa = sA + kk + tg;
        const float* pb = sB + kk + tg;
        unsigned a00 = __float_as_uint(pa[(m0w+g)*36]);
        unsigned a01 = __float_as_uint(pa[(m0w+g+8)*36]);
        unsigned a02 = __float_as_uint(pa[(m0w+g)*36 + 4]);
        unsigned a03 = __float_as_uint(pa[(m0w+g+8)*36 + 4]);
        unsigned a10 = __float_as_uint(pa[(m0w+16+g)*36]);
        unsigned a11 = __float_as_uint(pa[(m0w+24+g)*36]);
        unsigned a12 = __float_as_uint(pa[(m0w+16+g)*36 + 4]);
        unsigned a13 = __float_as_uint(pa[(m0w+24+g)*36 + 4]);
        unsigned b00 = __float_as_uint(pb[(n0w+g)*36]);
        unsigned b01 = __float_as_uint(pb[(n0w+g)*36 + 4]);
        unsigned b10 = __float_as_uint(pb[(n0w+8+g)*36]);
        unsigned b11 = __float_as_uint(pb[(n0w+8+g)*36 + 4]);
        mma8(acc[0][0], a00,a01,a02,a03, b00,b01);
        mma8(acc[0][1], a00,a01,a02,a03, b10,b11);
        mma8(acc[1][0], a10,a11,a12,a13, b00,b01);
        mma8(acc[1][1], a10,a11,a12,a13, b10,b11);
    }
}
__global__ void __launch_bounds__(256) gemm64_tf32(const float* __restrict__ A, int lda, int K,
                                                   const float* __restrict__ BT, int ldb,
                                                   float* __restrict__ C, int N, int mode){
    __shared__ float sA[64*36];
    __shared__ float sB[64*36];
    const int tid = threadIdx.x, lane = tid & 31, warp = tid >> 5;
    const int g = lane >> 2, tg = lane & 3;
    const int m0 = blockIdx.y*64, n0 = blockIdx.x*64;
    const int m0w = (warp & 1)*32, n0w = (warp >> 1)*16;
    float acc[2][2][4] = {};
    const int nst = (K + 31)/32;
    for (int s = 0; s < nst; s++){
        int k0 = s*32;
        __syncthreads();
        stage_load(A + (size_t)m0*lda + k0, lda, BT + (size_t)n0*ldb + k0, ldb,
                   sA, sB, tid, K - k0);
        __syncthreads();
        mma_tile_step(sA, sB, m0w, n0w, g, tg, acc);
    }
    #pragma unroll
    for (int fm = 0; fm < 2; fm++)
        #pragma unroll
        for (int fn = 0; fn < 2; fn++){
            int r = m0 + m0w + fm*16 + g;
            int c = n0 + n0w + fn*8 + tg*2;
            int m1 = r, m2 = r + 8;
            if (mode){
                m1 = (r & (TP_-1))*B_ + (r >> 9);
                m2 = ((r+8) & (TP_-1))*B_ + ((r+8) >> 9);
            }
            *(float2*)(C + (size_t)m1*N + c) = make_float2(acc[fm][fn][0], acc[fm][fn][1]);
            *(float2*)(C + (size_t)m2*N + c) = make_float2(acc[fm][fn][2], acc[fm][fn][3]);
        }
}

// ---------------- resident-B mma + cp.async ring GEMM (persist) ----------------
template<int LB>
__device__ __forceinline__ void mma_step_resB(const float* sAslot, const float* sW, int koff,
                                              int m0w, int n0w, int g, int tg, float acc[2][2][4]){
    #pragma unroll
    for (int kk = 0; kk < 32; kk += 8){
        const float* pa = sAslot + kk + tg;
        const float* pb = sW + koff + kk + tg;
        unsigned a00 = __float_as_uint(pa[(m0w+g)*36]);
        unsigned a01 = __float_as_uint(pa[(m0w+g+8)*36]);
        unsigned a02 = __float_as_uint(pa[(m0w+g)*36 + 4]);
        unsigned a03 = __float_as_uint(pa[(m0w+g+8)*36 + 4]);
        unsigned a10 = __float_as_uint(pa[(m0w+16+g)*36]);
        unsigned a11 = __float_as_uint(pa[(m0w+24+g)*36]);
        unsigned a12 = __float_as_uint(pa[(m0w+16+g)*36 + 4]);
        unsigned a13 = __float_as_uint(pa[(m0w+24+g)*36 + 4]);
        unsigned b00 = __float_as_uint(pb[(n0w+g)*LB]);
        unsigned b01 = __float_as_uint(pb[(n0w+g)*LB + 4]);
        unsigned b10 = __float_as_uint(pb[(n0w+8+g)*LB]);
        unsigned b11 = __float_as_uint(pb[(n0w+8+g)*LB + 4]);
        mma8(acc[0][0], a00,a01,a02,a03, b00,b01);
        mma8(acc[0][1], a00,a01,a02,a03, b10,b11);
        mma8(acc[1][0], a10,a11,a12,a13, b00,b01);
        mma8(acc[1][1], a10,a11,a12,a13, b10,b11);
    }
}

template<int LB, int NST>
__device__ __forceinline__ void gemm_ring(const float* __restrict__ Ag, int lda,
                                          float* sm, const float* sW, unsigned sbase, int tid,
                                          int m0w, int n0w, int g, int tg, float acc[2][2][4]){
    const int row1 = tid >> 3, c41 = (tid & 7)*4;
    const int f2 = tid + 256;
    const int row2 = f2 >> 3, c42 = (f2 & 7)*4;
    #pragma unroll
    for (int p = 0; p < 3; p++){
        unsigned sb = sbase + (unsigned)((p & 3)*RING_SLOT_)*4u;
        cpa16(sb + (unsigned)(row1*36 + c41)*4u, Ag + (size_t)row1*lda + p*32 + c41);
        cpa16(sb + (unsigned)(row2*36 + c42)*4u, Ag + (size_t)row2*lda + p*32 + c42);
        CP_COMMIT();
    }
    #pragma unroll 1
    for (int s = 0; s < NST; s++){
        CP_WAIT2();
        __syncthreads();
        if (s + 3 < NST){
            int p = s + 3;
            unsigned sb = sbase + (unsigned)((p & 3)*RING_SLOT_)*4u;
            cpa16(sb + (unsigned)(row1*36 + c41)*4u, Ag + (size_t)row1*lda + p*32 + c41);
            cpa16(sb + (unsigned)(row2*36 + c42)*4u, Ag + (size_t)row2*lda + p*32 + c42);
        }
        CP_COMMIT();
        mma_step_resB<LB>(sm + (s & 3)*RING_SLOT_, sW, s*32, m0w, n0w, g, tg, acc);
    }
    CP_WAIT0();
    __syncthreads();
}

// ---------------- persistent recurrent kernel ----------------
// Roles: last 64 bids = P3 (hWhh reg-GEMM + P2 + ctx reg-GEMM + LSTM); others = P2 only.
// P2: CTA bid<npair owns {2bid, 2bid+1}; others one tail batch.
// Tokens: 2 per step. All CTAs set 2st+1 after P2; P3 set 2st+2 after LSTM.
__global__ void __launch_bounds__(256, 1) persist_kernel(
    const float* __restrict__ input_q, const float* __restrict__ mask_q,
    const float* __restrict__ mask_p,  const float* __restrict__ b_att,
    const float* __restrict__ w_att,   float* __restrict__ out, int nctas)
{
    extern __shared__ float sm[];
    const int tid = threadIdx.x, bid = blockIdx.x;
    const int lane = tid & 31, warp = tid >> 5;
    const int g = lane >> 2, tg = lane & 3;
    const int m0w = (warp & 1)*32, n0w = (warp >> 1)*16;
    const int p3base = nctas - 64;
    const bool isP3 = (bid >= p3base);
    const unsigned sbase = (unsigned)__cvta_generic_to_shared(sm);

    int p3_b0 = 0, p3_j0 = 0;
    if (isP3){
        int p = bid - p3base; p3_b0 = (p >> 4)*64; p3_j0 = (p & 15)*64;
    }

    // P2 static pair assignment
    const int npair = (B_ > nctas) ? (B_ - nctas) : 0;
    int pb0 = (bid < npair) ? 2*bid : npair + bid;
    int pb1 = (bid < npair) ? 2*bid + 1 : -1;
    if (pb0 >= B_) pb0 = -1;

    // w_att as half2 pairs; lane covers pairs 4*lane..4*lane+3
    __half2 wv2[4];
    #pragma unroll
    for (int i = 0; i < 4; i++)
        wv2[i] = __floats2half2_rn(w_att[8*lane + 2*i], w_att[8*lane + 2*i + 1]);
    const float batt = b_att[tid];

    // resident tiles
    __half2* sWr = (__half2*)(sm + 1280);   // middle only: col-major stride 129
    if (isP3){
        float* sW1 = sm + W1_OFF_;          // Whh tile (rows H_+p3_j0+r of d_W2T)
        for (int i = tid; i < 64*64; i += 256){
            int r = i >> 6, c4 = (i & 63)*4;
            *(float4*)(sW1 + r*260 + c4) = *(const float4*)(d_W2T + (size_t)(H_+p3_j0+r)*H_ + c4);
        }
        float* sW2 = sm + W2_OFF_;          // Wq tile
        for (int i = tid; i < 64*80; i += 256){
            int r = i / 80, c4 = (i % 80)*4;
            *(float4*)(sW2 + r*324 + c4) = *(const float4*)(d_WqT2 + (size_t)(p3_j0+r)*KP_ + c4);
        }
    } else {
        for (int i = tid; i < 128*256; i += 256){
            int k2 = i >> 8, c = i & 255;
            sWr[c*129 + k2] = d_WrH[i];
        }
    }
    for (int i = bid*256 + tid; i < B_*H_; i += nctas*256){ d_h[i] = 0.f; d_c[i] = 0.f; }
    for (int i = bid*256 + tid; i < B_*KP_; i += nctas*256) d_ctx[i] = 0.f;
    grid_bar(nctas);

    for (int st = 0; st < TP_; st++){
        const unsigned base = 2u*(unsigned)st;

        // L2 prefetch of this step's cold slabs
        {
            const float* pwb = d_pW + (size_t)st*B_*H_;
            if (tid < 8){
                if (pb0 >= 0) pref_l2(pwb + pb0*H_ + tid*32);
                if (pb1 >= 0) pref_l2(pwb + pb1*H_ + tid*32);
            }
            if (isP3 && tid < 128)
                pref_l2(d_ppre + ((size_t)st*B_ + p3_b0 + (tid >> 1))*G4_
                        + p3_j0 + (tid & 1)*32);
        }

        // ---- wait for prev-step h ----
        wait_ge(p3base, 64, base);

        float acc[2][2][4] = {};
        if (isP3){
            // hWhh tile GEMM into registers (stays live through P2)
            gemm_ring<260, 8>(d_h + (size_t)p3_b0*H_, H_, sm, sm + W1_OFF_,
                              sbase, tid, m0w, n0w, g, tg, acc);
        }

        // ======== P2: attention, both batches interleaved, local hWr ========
        {
            float* attA = sm;                           // 256
            float* attB = sm + 256;                     // 256
            __half2* att2A = (__half2*)(sm + 512);      // 128 half2
            __half2* att2B = (__half2*)(sm + 640);      // 128 half2
            float* sScA = sm + 768;  float* sScB = sm + 832;
            float* sAlA = sm + 896;  float* sAlB = sm + 960;
            __half2* hA2 = (__half2*)(sm + 1024);       // 128 half2
            __half2* hB2 = (__half2*)(sm + 1152);       // 128 half2
            const bool okA = (pb0 >= 0), okB = (pb1 >= 0);

            // pack h rows to half2
            __syncthreads();
            if (tid < 128){
                if (okA) hA2[tid] = __floats2half2_rn(d_h[pb0*H_ + 2*tid], d_h[pb0*H_ + 2*tid + 1]);
            } else {
                int t = tid - 128;
                if (okB) hB2[t] = __floats2half2_rn(d_h[pb1*H_ + 2*t], d_h[pb1*H_ + 2*t + 1]);
            }
            __syncthreads();
            // local hWr: thread c = column tid
            {
                float accA = 0.f, accB = 0.f;
                if (isP3){
                    const __half2* wr = d_WrH + tid;
                    #pragma unroll 8
                    for (int k2 = 0; k2 < 128; k2++){
                        float2 wf = __half22float2(wr[k2*256]);
                        if (okA){ float2 ha = __half22float2(hA2[k2]);
                                  accA = fmaf(wf.x, ha.x, accA); accA = fmaf(wf.y, ha.y, accA); }
                        if (okB){ float2 hb = __half22float2(hB2[k2]);
                                  accB = fmaf(wf.x, hb.x, accB); accB = fmaf(wf.y, hb.y, accB); }
                    }
                } else {
                    const __half2* wr = sWr + tid*129;
                    #pragma unroll 8
                    for (int k2 = 0; k2 < 128; k2++){
                        float2 wf = __half22float2(wr[k2]);
                        if (okA){ float2 ha = __half22float2(hA2[k2]);
                                  accA = fmaf(wf.x, ha.x, accA); accA = fmaf(wf.y, ha.y, accA); }
                        if (okB){ float2 hb = __half22float2(hB2[k2]);
                                  accB = fmaf(wf.x, hb.x, accB); accB = fmaf(wf.y, hb.y, accB); }
                    }
                }
                if (okA) attA[tid] = accA + batt + d_pW[((size_t)st*B_ + pb0)*H_ + tid];
                if (okB) attB[tid] = accB + batt + d_pW[((size_t)st*B_ + pb1)*H_ + tid];
            }
            __syncthreads();
            if (tid < 128){
                if (okA) att2A[tid] = __floats2half2_rn(attA[2*tid], attA[2*tid+1]);
            } else {
                int t = tid - 128;
                if (okB) att2B[t] = __floats2half2_rn(attB[2*t], attB[2*t+1]);
            }
            __syncthreads();
            // ---- scores: 4 warps per batch, 16 tq per warp ----
            {
                const int wb = warp >> 2;
                const int wi = warp & 3;
                const int b = wb ? pb1 : pb0;
                if (b >= 0){
                    __half2* att2 = wb ? att2B : att2A;
                    float* sSc = wb ? sScB : sScA;
                    __half2 av2[4];
                    {
                        float4 avf = *(float4*)(att2 + 4*lane);
                        __half2* ah = (__half2*)&avf;
                        av2[0] = ah[0]; av2[1] = ah[1]; av2[2] = ah[2]; av2[3] = ah[3];
                    }
                    #pragma unroll
                    for (int it = 0; it < 16; it++){
                        int tq = wi + it*4;
                        float4 q4 = *(const float4*)(d_qproj2 + (size_t)(b*TQ_ + tq)*128 + 4*lane);
                        __half2* qh = (__half2*)&q4;
                        __half2 p0 = __hmul2(tanh2(__hadd2(qh[0], av2[0])), wv2[0]);
                        __half2 p1 = __hmul2(tanh2(__hadd2(qh[1], av2[1])), wv2[1]);
                        __half2 p2 = __hmul2(tanh2(__hadd2(qh[2], av2[2])), wv2[2]);
                        __half2 p3 = __hmul2(tanh2(__hadd2(qh[3], av2[3])), wv2[3]);
                        __half2 sum2 = __hadd2(__hadd2(p0, p1), __hadd2(p2, p3));
                        float2 f = __half22float2(sum2);
                        float s = f.x + f.y;
                        #pragma unroll
                        for (int off = 16; off; off >>= 1)
                            s += __shfl_xor_sync(0xffffffffu, s, off);
                        if (lane == 0) sSc[tq] = s;
                    }
                }
            }
            __syncthreads();
            // ---- softmax: warp 0 -> A, warp 4 -> B ----
            if ((warp == 0 && okA) || (warp == 4 && okB)){
                const int wb = warp >> 2;
                float* sSc = wb ? sScB : sScA;
                float* sAl = wb ? sAlB : sAlA;
                const int b = wb ? pb1 : pb0;
                float s0 = sSc[lane], s1 = sSc[lane+32];
                if (!(mask_q[b*TQ_ + lane]      > 0.f)) s0 = -1e9f;
                if (!(mask_q[b*TQ_ + lane + 32] > 0.f)) s1 = -1e9f;
                float mx = fmaxf(s0, s1);
                #pragma unroll
                for (int off = 16; off; off >>= 1)
                    mx = fmaxf(mx, __shfl_xor_sync(0xffffffffu, mx, off));
                float e0 = __expf(s0 - mx), e1 = __expf(s1 - mx);
                float sum = e0 + e1;
                #pragma unroll
                for (int off = 16; off; off >>= 1)
                    sum += __shfl_xor_sync(0xffffffffu, sum, off);
                float inv = __frcp_rn(sum);
                sAl[lane]      = e0 * inv;
                sAl[lane + 32] = e1 * inv;
            }
            __syncthreads();
            // ---- ctx: threads 0-127 -> A, 128-255 -> B ----
            {
                const int half = tid >> 7;
                const int b = half ? pb1 : pb0;
                const int ch = tid & 127;
                if (b >= 0 && ch < 75){
                    const float* sAl = half ? sAlB : sAlA;
                    const float* iqb = input_q + (size_t)b*TQ_*DPQ_ + ch*4;
                    unsigned long long acc0 = 0ull, acc1 = 0ull;
                    #pragma unroll 4
                    for (int tq = 0; tq < TQ_; tq++){
                        float a = sAl[tq];
                        unsigned long long a2 = packf2(a, a);
                        ulonglong2 v = *(const ulonglong2*)(iqb + (size_t)tq*DPQ_);
                        acc0 = ffma2_(v.x, a2, acc0);
                        acc1 = ffma2_(v.y, a2, acc1);
                    }
                    float2 r0 = unpackf2(acc0), r1 = unpackf2(acc1);
                    *(float4*)(d_ctx + b*KP_ + 4*ch) = make_float4(r0.x, r0.y, r1.x, r1.y);
                }
            }
        }
        set_flag(bid, base + 1);

        // ======== P3: ctx GEMM (accumulating onto hWhh acc) + fused LSTM ========
        if (isP3){
            wait_ge(0, nctas, base + 1);
            gemm_ring<324, 10>(d_ctx + (size_t)p3_b0*KP_, KP_, sm, sm + W2_OFF_,
                               sbase, tid, m0w, n0w, g, tg, acc);
            float* sG = sm + SG_OFF_;
            #pragma unroll
            for (int fm = 0; fm < 2; fm++)
                #pragma unroll
                for (int fn = 0; fn < 2; fn++){
                    int rl = m0w + fm*16 + g;
                    int cl = n0w + fn*8 + tg*2;
                    sG[rl*68 + cl]         = acc[fm][fn][0];
                    sG[rl*68 + cl + 1]     = acc[fm][fn][1];
                    sG[(rl+8)*68 + cl]     = acc[fm][fn][2];
                    sG[(rl+8)*68 + cl + 1] = acc[fm][fn][3];
                }
            __syncthreads();
            #pragma unroll
            for (int u = 0; u < 4; u++){
                int idx = tid + u*256;          // 64 b x 16 h
                int bl = idx >> 4, hl = idx & 15;
                int b = p3_b0 + bl;
                int j = p3_j0 + hl*4;
                int hg = (p3_j0 >> 2) + hl;
                float4 gm = *(float4*)(sG + bl*68 + hl*4);
                float4 pp = __ldcs((const float4*)(d_ppre + ((size_t)st*B_ + b)*G4_ + j));
                float4 bbv = *(const float4*)(d_bias + j);
                float gi = gm.x + pp.x + bbv.x;
                float gf = gm.y + pp.y + bbv.y;
                float gg = gm.z + pp.z + bbv.z;
                float go = gm.w + pp.w + bbv.w;
                float ig = sigm2(gi), fg = sigm2(gf);
                float gt = tanha(gg), og = sigm2(go);
                float c_old = d_c[b*H_ + hg];
                float h_old = d_h[b*H_ + hg];
                float c_new = fg*c_old + ig*gt;
                float h_new = og * tanha(c_new);
                float m = mask_p[b*TP_ + st];
                h_new = h_new*m + h_old*(1.f - m);
                c_new = c_new*m + c_old*(1.f - m);
                d_h[b*H_ + hg] = h_new;
                d_c[b*H_ + hg] = c_new;
                out[((size_t)b*TP_ + st)*H_ + hg] = h_new;
            }
            set_flag(bid, base + 2);
        }
    }
}

// ---------------- launch ----------------
extern "C" void kernel_launch(void* const* d_in, const int* in_sizes, int n_in,
                              void* d_out, int out_size) {
    const float* input_p = (const float*)d_in[0];
    const float* mask_p  = (const float*)d_in[1];
    const float* input_q = (const float*)d_in[2];
    const float* mask_q  = (const float*)d_in[3];
    const float* Wq      = (const float*)d_in[4];
    const float* Wp      = (const float*)d_in[5];
    const float* Wr      = (const float*)d_in[6];
    const float* b_att   = (const float*)d_in[7];
    const float* w_att   = (const float*)d_in[8];
    const float* W_ih    = (const float*)d_in[9];
    const float* W_hh    = (const float*)d_in[10];
    const float* b_ih    = (const float*)d_in[11];
    const float* b_hh    = (const float*)d_in[12];
    float* out = (float*)d_out;

    int dev = 0; cudaGetDevice(&dev);
    int nsm = 0; cudaDeviceGetAttribute(&nsm, cudaDevAttrMultiProcessorCount, dev);
    if (nsm < 144) nsm = 148;
    if (nsm > 256) nsm = 256;

    float *p_qproj, *p_pW, *p_ppre, *p_WqTn, *p_WpTn, *p_WihpT2;
    cudaGetSymbolAddress((void**)&p_qproj,   d_qproj);
    cudaGetSymbolAddress((void**)&p_pW,      d_pW);
    cudaGetSymbolAddress((void**)&p_ppre,    d_ppre);
    cudaGetSymbolAddress((void**)&p_WqTn,    d_WqTn);
    cudaGetSymbolAddress((void**)&p_WpTn,    d_WpTn);
    cudaGetSymbolAddress((void**)&p_WihpT2,  d_WihpT2);

    cudaFuncSetAttribute(persist_kernel, cudaFuncAttributeMaxDynamicSharedMemorySize,
                         SMEM_FLOATS_*4);

    prep_kernel<<<512, 256>>>(Wq, Wp, Wr, W_ih, W_hh, b_ih, b_hh);
    reset_kernel<<<1, 256>>>();

    gemm64_tf32<<<dim3(4, 256), 256>>>(input_q, DPQ_, DPQ_, p_WqTn, KP_, p_qproj, H_, 0);
    qconv_kernel<<<8192, 256>>>();
    gemm64_tf32<<<dim3(4, 2048), 256>>>(input_p, DPQ_, DPQ_, p_WpTn, KP_, p_pW, H_, 1);
    gemm64_tf32<<<dim3(16, 2048), 256>>>(input_p, DPQ_, DPQ_, p_WihpT2, KP_, p_ppre, G4_, 1);

    persist_kernel<<<nsm, 256, SMEM_FLOATS_*4>>>(input_q, mask_q, mask_p,
                                                 b_att, w_att, out, nsm);
}

// round 17
// speedup vs baseline: 1.3391x; 1.3391x over previous
#include <cuda_runtime.h>
#include <cuda_fp16.h>

#define B_   256
#define TP_  512
#define TQ_  64
#define DPQ_ 300
#define KP_  320     // padded K for 300-dim GEMMs
#define H_   256
#define G4_  1024

// smem layout (floats) for persist kernel
#define RING_SLOT_ 2304        // 64 rows x 36
#define W_OFF_     9216        // after 4 ring slots
#define SG_OFF_    29952       // after P3 weight tile (64*324)
#define SMEM_FLOATS_ 34304     // + sG 64*68 -> 137216 bytes

// ---------------- device scratch ----------------
__device__ float  d_qproj[B_*TQ_*H_];       // fp32 (gemm output)
__device__ __half2 d_qproj2[B_*TQ_*128];    // half2 pairs (h=2j, 2j+1)
__device__ float d_pW[TP_*B_*H_];           // time-major [st][b][h]
__device__ float d_ppre[TP_*B_*G4_];        // time-major [st][b][j] (permuted gate cols)
__device__ float d_W2T[1280*H_];            // n-major [n][k]; n>=256 = permuted Whh cols
__device__ float d_WqT2[G4_*KP_];           // n-major permuted [j][k], k>=300 zero
__device__ float d_WihpT2[G4_*KP_];
__device__ float d_WqTn[H_*KP_];
__device__ float d_WpTn[H_*KP_];
__device__ float d_bias[G4_];
__device__ float d_hWr[B_*H_];
__device__ float d_hWhh[B_*G4_];
__device__ float d_ctx[B_*KP_];
__device__ float d_h[B_*H_];
__device__ float d_c[B_*H_];
__device__ unsigned g_cnt;
__device__ unsigned g_gen;
__device__ unsigned d_cnts[96];   // [0]=cnt_h, [32]=cnt_r, [64]=cnt_p2 (separate 128B lines)

// ---------------- helpers ----------------
__device__ __forceinline__ float tanha(float x){
    float y; asm("tanh.approx.f32 %0, %1;" : "=f"(y) : "f"(x)); return y;
}
__device__ __forceinline__ __half2 tanh2(__half2 x){
    unsigned u = *(unsigned*)&x, r;
    asm("tanh.approx.f16x2 %0, %1;" : "=r"(r) : "r"(u));
    return *(__half2*)&r;
}
__device__ __forceinline__ float sigm2(float x){
    return fmaf(tanha(0.5f*x), 0.5f, 0.5f);
}
__device__ __forceinline__ float to_tf32(float x){
    unsigned u; asm("cvt.rna.tf32.f32 %0, %1;" : "=r"(u) : "f"(x));
    return __uint_as_float(u);
}
// packed fp32 FMA (sm_100a+)
__device__ __forceinline__ unsigned long long ffma2_(unsigned long long a,
                                                     unsigned long long b,
                                                     unsigned long long c){
    unsigned long long d;
    asm("fma.rn.f32x2 %0, %1, %2, %3;" : "=l"(d) : "l"(a), "l"(b), "l"(c));
    return d;
}
__device__ __forceinline__ unsigned long long packf2(float lo, float hi){
    unsigned long long u;
    asm("mov.b64 %0, {%1, %2};" : "=l"(u) : "f"(lo), "f"(hi));
    return u;
}
__device__ __forceinline__ float2 unpackf2(unsigned long long u){
    float lo, hi;
    asm("mov.b64 {%0, %1}, %2;" : "=f"(lo), "=f"(hi) : "l"(u));
    return make_float2(lo, hi);
}
__device__ __forceinline__ void mma8(float* d, unsigned a0, unsigned a1, unsigned a2, unsigned a3,
                                     unsigned b0, unsigned b1){
    asm volatile("mma.sync.aligned.m16n8k8.row.col.f32.tf32.tf32.f32 "
                 "{%0,%1,%2,%3},{%4,%5,%6,%7},{%8,%9},{%0,%1,%2,%3};"
                 : "+f"(d[0]), "+f"(d[1]), "+f"(d[2]), "+f"(d[3])
                 : "r"(a0), "r"(a1), "r"(a2), "r"(a3), "r"(b0), "r"(b1));
}
__device__ __forceinline__ void cpa16(unsigned s, const float* g){
    asm volatile("cp.async.cg.shared.global [%0], [%1], 16;" :: "r"(s), "l"(g));
}
#define CP_COMMIT() asm volatile("cp.async.commit_group;" ::: "memory")
#define CP_WAIT2()  asm volatile("cp.async.wait_group 2;"  ::: "memory")
#define CP_WAIT0()  asm volatile("cp.async.wait_group 0;"  ::: "memory")

__device__ __forceinline__ void pref_l2(const float* p){
    asm volatile("prefetch.global.L2 [%0];" :: "l"(p));
}
__device__ __forceinline__ unsigned ldacq(const unsigned* p){
    unsigned v; asm volatile("ld.acquire.gpu.global.u32 %0, [%1];" : "=r"(v) : "l"(p) : "memory");
    return v;
}
// single-thread, single-line counter wait with backoff
__device__ __forceinline__ void wait_cnt(const unsigned* p, unsigned tgt){
    if (threadIdx.x == 0){
        if (ldacq(p) < tgt){
            while (ldacq(p) < tgt) __nanosleep(100);
        }
    }
    __syncthreads();
}
// CTA-wide release increment (one red per CTA)
__device__ __forceinline__ void inc_cnt(unsigned* p){
    __syncthreads();
    if (threadIdx.x == 0)
        asm volatile("red.release.gpu.global.add.u32 [%0], %1;" :: "l"(p), "r"(1u) : "memory");
}

// ---------------- PROVEN grid barrier (post-init only) ----------------
__device__ __forceinline__ void grid_bar(int nctas){
    __syncthreads();
    if (threadIdx.x == 0){
        __threadfence();
        unsigned g = *(volatile unsigned*)&g_gen;
        unsigned prev = atomicAdd(&g_cnt, 1u);
        if (prev == (unsigned)(nctas - 1)){
            atomicExch(&g_cnt, 0u);
            __threadfence();
            atomicAdd(&g_gen, 1u);
        } else {
            while (*(volatile unsigned*)&g_gen == g) { __nanosleep(32); }
        }
        __threadfence();
    }
    __syncthreads();
}

__device__ __forceinline__ int gperm(int j){ return (j & 3)*H_ + (j >> 2); }

// ---------------- K0: weight prep ----------------
__global__ void prep_kernel(const float* __restrict__ Wq, const float* __restrict__ Wp,
                            const float* __restrict__ Wr, const float* __restrict__ Wih,
                            const float* __restrict__ Whh,
                            const float* __restrict__ bih, const float* __restrict__ bhh){
    int idx0 = blockIdx.x*blockDim.x + threadIdx.x;
    int stride = gridDim.x*blockDim.x;
    for (int i = idx0; i < 1280*H_; i += stride){
        int n = i / H_, k = i - n*H_;
        float v = (n < H_) ? Wr[k*H_ + n] : Whh[gperm(n - H_)*H_ + k];
        d_W2T[i] = to_tf32(v);
    }
    for (int i = idx0; i < G4_*KP_; i += stride){
        int j = i / KP_, k = i - j*KP_;
        int a = gperm(j);
        d_WqT2[i]   = (k < DPQ_) ? to_tf32(Wih[a*600 + 300 + k]) : 0.f;
        d_WihpT2[i] = (k < DPQ_) ? to_tf32(Wih[a*600 + k])       : 0.f;
    }
    for (int i = idx0; i < H_*KP_; i += stride){
        int n = i / KP_, k = i - n*KP_;
        d_WqTn[i] = (k < DPQ_) ? to_tf32(Wq[k*H_ + n]) : 0.f;
        d_WpTn[i] = (k < DPQ_) ? to_tf32(Wp[k*H_ + n]) : 0.f;
    }
    for (int j = idx0; j < G4_; j += stride){
        int a = gperm(j);
        d_bias[j] = bih[a] + bhh[a];
    }
}

__global__ void reset_kernel(){
    if (blockIdx.x == 0 && threadIdx.x < 96) d_cnts[threadIdx.x] = 0u;
}

// ---------------- qproj fp32 -> half2 pairs ----------------
__global__ void qconv_kernel(){
    int i = blockIdx.x*blockDim.x + threadIdx.x;
    if (i < B_*TQ_*128)
        d_qproj2[i] = __floats2half2_rn(d_qproj[2*i], d_qproj[2*i+1]);
}

// ---------------- upfront tf32 GEMM (proven) ----------------
__device__ __forceinline__ void stage_load(const float* __restrict__ Ag, int lda,
                                           const float* __restrict__ Bg, int ldb,
                                           float* sA, float* sB, int tid, int krem){
    #pragma unroll
    for (int i = 0; i < 2; i++){
        int f = tid + i*256;
        int row = f >> 3, c4 = (f & 7)*4;
        float4 va = make_float4(0.f,0.f,0.f,0.f);
        if (c4 < krem) va = *(const float4*)(Ag + (size_t)row*lda + c4);
        *(float4*)(sA + row*36 + c4) = va;
        float4 vb = *(const float4*)(Bg + (size_t)row*ldb + c4);
        *(float4*)(sB + row*36 + c4) = vb;
    }
}
__device__ __forceinline__ void mma_tile_step(const float* sA, const float* sB,
                                              int m0w, int n0w, int g, int tg,
                                              float acc[2][2][4]){
    #pragma unroll
    for (int kk = 0; kk < 32; kk += 8){
        const float* pa = sA + kk + tg;
        const float* pb = sB + kk + tg;
        unsigned a00 = __float_as_uint(pa[(m0w+g)*36]);
        unsigned a01 = __float_as_uint(pa[(m0w+g+8)*36]);
        unsigned a02 = __float_as_uint(pa[(m0w+g)*36 + 4]);
        unsigned a03 = __float_as_uint(pa[(m0w+g+8)*36 + 4]);
        unsigned a10 = __float_as_uint(pa[(m0w+16+g)*36]);
        unsigned a11 = __float_as_uint(pa[(m0w+24+g)*36]);
        unsigned a12 = __float_as_uint(pa[(m0w+16+g)*36 + 4]);
        unsigned a13 = __float_as_uint(pa[(m0w+24+g)*36 + 4]);
        unsigned b00 = __float_as_uint(pb[(n0w+g)*36]);
        unsigned b01 = __float_as_uint(pb[(n0w+g)*36 + 4]);
        unsigned b10 = __float_as_uint(pb[(n0w+8+g)*36]);
        unsigned b11 = __float_as_uint(pb[(n0w+8+g)*36 + 4]);
        mma8(acc[0][0], a00,a01,a02,a03, b00,b01);
        mma8(acc[0][1], a00,a01,a02,a03, b10,b11);
        mma8(acc[1][0], a10,a11,a12,a13, b00,b01);
        mma8(acc[1][1], a10,a11,a12,a13, b10,b11);
    }
}
__global__ void __launch_bounds__(256) gemm64_tf32(const float* __restrict__ A, int lda, int K,
                                                   const float* __restrict__ BT, int ldb,
                                                   float* __restrict__ C, int N, int mode){
    __shared__ float sA[64*36];
    __shared__ float sB[64*36];
    const int tid = threadIdx.x, lane = tid & 31, warp = tid >> 5;
    const int g = lane >> 2, tg = lane & 3;
    const int m0 = blockIdx.y*64, n0 = blockIdx.x*64;
    const int m0w = (warp & 1)*32, n0w = (warp >> 1)*16;
    float acc[2][2][4] = {};
    const int nst = (K + 31)/32;
    for (int s = 0; s < nst; s++){
        int k0 = s*32;
        __syncthreads();
        stage_load(A + (size_t)m0*lda + k0, lda, BT + (size_t)n0*ldb + k0, ldb,
                   sA, sB, tid, K - k0);
        __syncthreads();
        mma_tile_step(sA, sB, m0w, n0w, g, tg, acc);
    }
    #pragma unroll
    for (int fm = 0; fm < 2; fm++)
        #pragma unroll
        for (int fn = 0; fn < 2; fn++){
            int r = m0 + m0w + fm*16 + g;
            int c = n0 + n0w + fn*8 + tg*2;
            int m1 = r, m2 = r + 8;
            if (mode){
                m1 = (r & (TP_-1))*B_ + (r >> 9);
                m2 = ((r+8) & (TP_-1))*B_ + ((r+8) >> 9);
            }
            *(float2*)(C + (size_t)m1*N + c) = make_float2(acc[fm][fn][0], acc[fm][fn][1]);
            *(float2*)(C + (size_t)m2*N + c) = make_float2(acc[fm][fn][2], acc[fm][fn][3]);
        }
}

// ---------------- resident-B mma + cp.async ring GEMM (persist) ----------------
template<int LB>
__device__ __forceinline__ void mma_step_resB(const float* sAslot, const float* sW, int koff,
                                              int m0w, int n0w, int g, int tg, float acc[2][2][4]){
    #pragma unroll
    for (int kk = 0; kk < 32; kk += 8){
        const float* pa = sAslot + kk + tg;
        const float* pb = sW + koff + kk + tg;
        unsigned a00 = __float_as_uint(pa[(m0w+g)*36]);
        unsigned a01 = __float_as_uint(pa[(m0w+g+8)*36]);
        unsigned a02 = __float_as_uint(pa[(m0w+g)*36 + 4]);
        unsigned a03 = __float_as_uint(pa[(m0w+g+8)*36 + 4]);
        unsigned a10 = __float_as_uint(pa[(m0w+16+g)*36]);
        unsigned a11 = __float_as_uint(pa[(m0w+24+g)*36]);
        unsigned a12 = __float_as_uint(pa[(m0w+16+g)*36 + 4]);
        unsigned a13 = __float_as_uint(pa[(m0w+24+g)*36 + 4]);
        unsigned b00 = __float_as_uint(pb[(n0w+g)*LB]);
        unsigned b01 = __float_as_uint(pb[(n0w+g)*LB + 4]);
        unsigned b10 = __float_as_uint(pb[(n0w+8+g)*LB]);
        unsigned b11 = __float_as_uint(pb[(n0w+8+g)*LB + 4]);
        mma8(acc[0][0], a00,a01,a02,a03, b00,b01);
        mma8(acc[0][1], a00,a01,a02,a03, b10,b11);
        mma8(acc[1][0], a10,a11,a12,a13, b00,b01);
        mma8(acc[1][1], a10,a11,a12,a13, b10,b11);
    }
}

template<int LB, int NST>
__device__ __forceinline__ void gemm_ring(const float* __restrict__ Ag, int lda,
                                          float* sm, unsigned sbase, int tid,
                                          int m0w, int n0w, int g, int tg, float acc[2][2][4]){
    const float* sW = sm + W_OFF_;
    const int row1 = tid >> 3, c41 = (tid & 7)*4;
    const int f2 = tid + 256;
    const int row2 = f2 >> 3, c42 = (f2 & 7)*4;
    #pragma unroll
    for (int p = 0; p < 3; p++){
        unsigned sb = sbase + (unsigned)((p & 3)*RING_SLOT_)*4u;
        cpa16(sb + (unsigned)(row1*36 + c41)*4u, Ag + (size_t)row1*lda + p*32 + c41);
        cpa16(sb + (unsigned)(row2*36 + c42)*4u, Ag + (size_t)row2*lda + p*32 + c42);
        CP_COMMIT();
    }
    #pragma unroll 1
    for (int s = 0; s < NST; s++){
        CP_WAIT2();
        __syncthreads();
        if (s + 3 < NST){
            int p = s + 3;
            unsigned sb = sbase + (unsigned)((p & 3)*RING_SLOT_)*4u;
            cpa16(sb + (unsigned)(row1*36 + c41)*4u, Ag + (size_t)row1*lda + p*32 + c41);
            cpa16(sb + (unsigned)(row2*36 + c42)*4u, Ag + (size_t)row2*lda + p*32 + c42);
        }
        CP_COMMIT();
        mma_step_resB<LB>(sm + (s & 3)*RING_SLOT_, sW, s*32, m0w, n0w, g, tg, acc);
    }
    CP_WAIT0();
    __syncthreads();
}

// ---------------- persistent recurrent kernel ----------------
// P1 tiles: bids 0..15 -> hWr; bids 16..79 -> hWhh. P3: last 64 bids.
// P2: CTA bid<npair owns {2bid, 2bid+1}; others one tail batch.
// Sync: 3 aggregated monotonic counters. cnt_h += 64/step (P3), cnt_r += 16/step (hWr CTAs),
//       cnt_p2 += nctas/step (all CTAs).
__global__ void __launch_bounds__(256, 1) persist_kernel(
    const float* __restrict__ input_q, const float* __restrict__ mask_q,
    const float* __restrict__ mask_p,  const float* __restrict__ b_att,
    const float* __restrict__ w_att,   float* __restrict__ out, int nctas)
{
    extern __shared__ float sm[];
    const int tid = threadIdx.x, bid = blockIdx.x;
    const int lane = tid & 31, warp = tid >> 5;
    const int g = lane >> 2, tg = lane & 3;
    const int m0w = (warp & 1)*32, n0w = (warp >> 1)*16;
    const int p3base = nctas - 64;
    const bool isP1 = (bid < 80);
    const bool isR  = (bid < 16);
    const bool isP3 = (bid >= p3base);
    const unsigned sbase = (unsigned)__cvta_generic_to_shared(sm);
    unsigned* cnt_h  = &d_cnts[0];
    unsigned* cnt_r  = &d_cnts[32];
    unsigned* cnt_p2 = &d_cnts[64];

    int p1_b0 = 0, p1_n0 = 0;
    if (isP1){
        if (isR){ p1_b0 = (bid >> 2)*64; p1_n0 = (bid & 3)*64; }
        else    { int idx = bid - 16; p1_b0 = (idx >> 4)*64; p1_n0 = H_ + (idx & 15)*64; }
    }
    int p3_b0 = 0, p3_j0 = 0;
    if (isP3){
        int p = bid - p3base; p3_b0 = (p >> 4)*64; p3_j0 = (p & 15)*64;
    }

    // P2 static pair assignment
    const int npair = (B_ > nctas) ? (B_ - nctas) : 0;
    int pb0 = (bid < npair) ? 2*bid : npair + bid;
    int pb1 = (bid < npair) ? 2*bid + 1 : -1;
    if (pb0 >= B_) pb0 = -1;

    // w_att as half2 pairs; lane covers pairs 4*lane..4*lane+3 (h = 8*lane..8*lane+7)
    __half2 wv2[4];
    #pragma unroll
    for (int i = 0; i < 4; i++)
        wv2[i] = __floats2half2_rn(w_att[8*lane + 2*i], w_att[8*lane + 2*i + 1]);

    if (isP1){
        float* sW = sm + W_OFF_;
        for (int i = tid; i < 64*64; i += 256){
            int r = i >> 6, c4 = (i & 63)*4;
            *(float4*)(sW + r*260 + c4) = *(const float4*)(d_W2T + (size_t)(p1_n0+r)*H_ + c4);
        }
    }
    if (isP3){
        float* sW = sm + W_OFF_;
        for (int i = tid; i < 64*80; i += 256){
            int r = i / 80, c4 = (i % 80)*4;
            *(float4*)(sW + r*324 + c4) = *(const float4*)(d_WqT2 + (size_t)(p3_j0+r)*KP_ + c4);
        }
    }
    for (int i = bid*256 + tid; i < B_*H_; i += nctas*256){ d_h[i] = 0.f; d_c[i] = 0.f; }
    for (int i = bid*256 + tid; i < B_*KP_; i += nctas*256) d_ctx[i] = 0.f;
    grid_bar(nctas);

    for (int st = 0; st < TP_; st++){
        // L2 prefetch of this step's cold slabs
        {
            const float* pwb = d_pW + (size_t)st*B_*H_;
            if (tid < 8){
                if (pb0 >= 0) pref_l2(pwb + pb0*H_ + tid*32);
                if (pb1 >= 0) pref_l2(pwb + pb1*H_ + tid*32);
            }
            if (isP3 && tid < 128)
                pref_l2(d_ppre + ((size_t)st*B_ + p3_b0 + (tid >> 1))*G4_
                        + p3_j0 + (tid & 1)*32);
        }

        // ======== P1 ========
        if (isP1){
            wait_cnt(cnt_h, 64u*(unsigned)st);
            float acc[2][2][4] = {};
            gemm_ring<260, 8>(d_h + (size_t)p1_b0*H_, H_, sm, sbase, tid, m0w, n0w, g, tg, acc);
            #pragma unroll
            for (int fm = 0; fm < 2; fm++)
                #pragma unroll
                for (int fn = 0; fn < 2; fn++){
                    int r = p1_b0 + m0w + fm*16 + g;
                    int c = p1_n0 + n0w + fn*8 + tg*2;
                    if (isR){
                        float ba0 = b_att[c], ba1 = b_att[c+1];
                        *(float2*)(d_hWr + r*H_ + c)     = make_float2(acc[fm][fn][0]+ba0, acc[fm][fn][1]+ba1);
                        *(float2*)(d_hWr + (r+8)*H_ + c) = make_float2(acc[fm][fn][2]+ba0, acc[fm][fn][3]+ba1);
                    } else {
                        int j = c - H_;
                        *(float2*)(d_hWhh + (size_t)r*G4_ + j)     = make_float2(acc[fm][fn][0], acc[fm][fn][1]);
                        *(float2*)(d_hWhh + (size_t)(r+8)*G4_ + j) = make_float2(acc[fm][fn][2], acc[fm][fn][3]);
                    }
                }
            if (isR) inc_cnt(cnt_r);
        }

        // ======== P2: attention, both batches interleaved ========
        wait_cnt(cnt_r, 16u*(unsigned)(st + 1));
        {
            float* attA = sm;                           // 256
            float* attB = sm + 256;                     // 256
            __half2* att2A = (__half2*)(sm + 512);      // 128 half2
            __half2* att2B = (__half2*)(sm + 640);      // 128 half2
            float* sScA = sm + 768;  float* sScB = sm + 832;
            float* sAlA = sm + 896;  float* sAlB = sm + 960;
            const bool okA = (pb0 >= 0), okB = (pb1 >= 0);

            if (okA) attA[tid] = __ldcg(&d_hWr[pb0*H_ + tid]) + d_pW[((size_t)st*B_ + pb0)*H_ + tid];
            if (okB) attB[tid] = __ldcg(&d_hWr[pb1*H_ + tid]) + d_pW[((size_t)st*B_ + pb1)*H_ + tid];
            __syncthreads();
            if (tid < 128){
                if (okA) att2A[tid] = __floats2half2_rn(attA[2*tid], attA[2*tid+1]);
            } else {
                int t = tid - 128;
                if (okB) att2B[t] = __floats2half2_rn(attB[2*t], attB[2*t+1]);
            }
            __syncthreads();
            // ---- scores: 4 warps per batch, 16 tq per warp ----
            {
                const int wb = warp >> 2;               // 0 -> A, 1 -> B
                const int wi = warp & 3;
                const int b = wb ? pb1 : pb0;
                if (b >= 0){
                    __half2* att2 = wb ? att2B : att2A;
                    float* sSc = wb ? sScB : sScA;
                    __half2 av2[4];
                    {
                        float4 avf = *(float4*)(att2 + 4*lane);
                        __half2* ah = (__half2*)&avf;
                        av2[0] = ah[0]; av2[1] = ah[1]; av2[2] = ah[2]; av2[3] = ah[3];
                    }
                    #pragma unroll
                    for (int it = 0; it < 16; it++){
                        int tq = wi + it*4;
                        float4 q4 = *(const float4*)(d_qproj2 + (size_t)(b*TQ_ + tq)*128 + 4*lane);
                        __half2* qh = (__half2*)&q4;
                        __half2 p0 = __hmul2(tanh2(__hadd2(qh[0], av2[0])), wv2[0]);
                        __half2 p1 = __hmul2(tanh2(__hadd2(qh[1], av2[1])), wv2[1]);
                        __half2 p2 = __hmul2(tanh2(__hadd2(qh[2], av2[2])), wv2[2]);
                        __half2 p3 = __hmul2(tanh2(__hadd2(qh[3], av2[3])), wv2[3]);
                        __half2 sum2 = __hadd2(__hadd2(p0, p1), __hadd2(p2, p3));
                        float2 f = __half22float2(sum2);
                        float s = f.x + f.y;
                        #pragma unroll
                        for (int off = 16; off; off >>= 1)
                            s += __shfl_xor_sync(0xffffffffu, s, off);
                        if (lane == 0) sSc[tq] = s;
                    }
                }
            }
            __syncthreads();
            // ---- softmax: warp 0 -> A, warp 4 -> B ----
            if ((warp == 0 && okA) || (warp == 4 && okB)){
                const int wb = warp >> 2;
                float* sSc = wb ? sScB : sScA;
                float* sAl = wb ? sAlB : sAlA;
                const int b = wb ? pb1 : pb0;
                float s0 = sSc[lane], s1 = sSc[lane+32];
                if (!(mask_q[b*TQ_ + lane]      > 0.f)) s0 = -1e9f;
                if (!(mask_q[b*TQ_ + lane + 32] > 0.f)) s1 = -1e9f;
                float mx = fmaxf(s0, s1);
                #pragma unroll
                for (int off = 16; off; off >>= 1)
                    mx = fmaxf(mx, __shfl_xor_sync(0xffffffffu, mx, off));
                float e0 = __expf(s0 - mx), e1 = __expf(s1 - mx);
                float sum = e0 + e1;
                #pragma unroll
                for (int off = 16; off; off >>= 1)
                    sum += __shfl_xor_sync(0xffffffffu, sum, off);
                float inv = __frcp_rn(sum);
                sAl[lane]      = e0 * inv;
                sAl[lane + 32] = e1 * inv;
            }
            __syncthreads();
            // ---- ctx: threads 0-127 -> A, 128-255 -> B; chunk of 4 dims, full 64 tq ----
            {
                const int half = tid >> 7;
                const int b = half ? pb1 : pb0;
                const int ch = tid & 127;
                if (b >= 0 && ch < 75){
                    const float* sAl = half ? sAlB : sAlA;
                    const float* iqb = input_q + (size_t)b*TQ_*DPQ_ + ch*4;
                    unsigned long long acc0 = 0ull, acc1 = 0ull;
                    #pragma unroll 4
                    for (int tq = 0; tq < TQ_; tq++){
                        float a = sAl[tq];
                        unsigned long long a2 = packf2(a, a);
                        ulonglong2 v = *(const ulonglong2*)(iqb + (size_t)tq*DPQ_);
                        acc0 = ffma2_(v.x, a2, acc0);
                        acc1 = ffma2_(v.y, a2, acc1);
                    }
                    float2 r0 = unpackf2(acc0), r1 = unpackf2(acc1);
                    *(float4*)(d_ctx + b*KP_ + 4*ch) = make_float4(r0.x, r0.y, r1.x, r1.y);
                }
            }
        }
        inc_cnt(cnt_p2);

        // ======== P3: gates GEMM + fused LSTM (last 64 CTAs) ========
        if (isP3){
            wait_cnt(cnt_p2, (unsigned)nctas*(unsigned)(st + 1));
            float acc[2][2][4] = {};
            gemm_ring<324, 10>(d_ctx + (size_t)p3_b0*KP_, KP_, sm, sbase, tid, m0w, n0w, g, tg, acc);
            float* sG = sm + SG_OFF_;
            #pragma unroll
            for (int fm = 0; fm < 2; fm++)
                #pragma unroll
                for (int fn = 0; fn < 2; fn++){
                    int rl = m0w + fm*16 + g;
                    int cl = n0w + fn*8 + tg*2;
                    sG[rl*68 + cl]         = acc[fm][fn][0];
                    sG[rl*68 + cl + 1]     = acc[fm][fn][1];
                    sG[(rl+8)*68 + cl]     = acc[fm][fn][2];
                    sG[(rl+8)*68 + cl + 1] = acc[fm][fn][3];
                }
            __syncthreads();
            #pragma unroll
            for (int u = 0; u < 4; u++){
                int idx = tid + u*256;          // 64 b x 16 h
                int bl = idx >> 4, hl = idx & 15;
                int b = p3_b0 + bl;
                int j = p3_j0 + hl*4;
                int hg = (p3_j0 >> 2) + hl;
                float4 gm = *(float4*)(sG + bl*68 + hl*4);
                float4 pp = __ldcs((const float4*)(d_ppre + ((size_t)st*B_ + b)*G4_ + j));
                float4 hh = __ldcg((const float4*)(d_hWhh + (size_t)b*G4_ + j));
                float4 bbv = *(const float4*)(d_bias + j);
                float gi = gm.x + pp.x + hh.x + bbv.x;
                float gf = gm.y + pp.y + hh.y + bbv.y;
                float gg = gm.z + pp.z + hh.z + bbv.z;
                float go = gm.w + pp.w + hh.w + bbv.w;
                float ig = sigm2(gi), fg = sigm2(gf);
                float gt = tanha(gg), og = sigm2(go);
                float c_old = d_c[b*H_ + hg];
                float h_old = d_h[b*H_ + hg];
                float c_new = fg*c_old + ig*gt;
                float h_new = og * tanha(c_new);
                float m = mask_p[b*TP_ + st];
                h_new = h_new*m + h_old*(1.f - m);
                c_new = c_new*m + c_old*(1.f - m);
                d_h[b*H_ + hg] = h_new;
                d_c[b*H_ + hg] = c_new;
                out[((size_t)b*TP_ + st)*H_ + hg] = h_new;
            }
            inc_cnt(cnt_h);
        }
    }
}

// ---------------- launch ----------------
extern "C" void kernel_launch(void* const* d_in, const int* in_sizes, int n_in,
                              void* d_out, int out_size) {
    const float* input_p = (const float*)d_in[0];
    const float* mask_p  = (const float*)d_in[1];
    const float* input_q = (const float*)d_in[2];
    const float* mask_q  = (const float*)d_in[3];
    const float* Wq      = (const float*)d_in[4];
    const float* Wp      = (const float*)d_in[5];
    const float* Wr      = (const float*)d_in[6];
    const float* b_att   = (const float*)d_in[7];
    const float* w_att   = (const float*)d_in[8];
    const float* W_ih    = (const float*)d_in[9];
    const float* W_hh    = (const float*)d_in[10];
    const float* b_ih    = (const float*)d_in[11];
    const float* b_hh    = (const float*)d_in[12];
    float* out = (float*)d_out;

    int dev = 0; cudaGetDevice(&dev);
    int nsm = 0; cudaDeviceGetAttribute(&nsm, cudaDevAttrMultiProcessorCount, dev);
    if (nsm < 144) nsm = 148;
    if (nsm > 256) nsm = 256;

    float *p_qproj, *p_pW, *p_ppre, *p_WqTn, *p_WpTn, *p_WihpT2;
    cudaGetSymbolAddress((void**)&p_qproj,   d_qproj);
    cudaGetSymbolAddress((void**)&p_pW,      d_pW);
    cudaGetSymbolAddress((void**)&p_ppre,    d_ppre);
    cudaGetSymbolAddress((void**)&p_WqTn,    d_WqTn);
    cudaGetSymbolAddress((void**)&p_WpTn,    d_WpTn);
    cudaGetSymbolAddress((void**)&p_WihpT2,  d_WihpT2);

    cudaFuncSetAttribute(persist_kernel, cudaFuncAttributeMaxDynamicSharedMemorySize,
                         SMEM_FLOATS_*4);

    prep_kernel<<<512, 256>>>(Wq, Wp, Wr, W_ih, W_hh, b_ih, b_hh);
    reset_kernel<<<1, 256>>>();

    gemm64_tf32<<<dim3(4, 256), 256>>>(input_q, DPQ_, DPQ_, p_WqTn, KP_, p_qproj, H_, 0);
    qconv_kernel<<<8192, 256>>>();
    gemm64_tf32<<<dim3(4, 2048), 256>>>(input_p, DPQ_, DPQ_, p_WpTn, KP_, p_pW, H_, 1);
    gemm64_tf32<<<dim3(16, 2048), 256>>>(input_p, DPQ_, DPQ_, p_WihpT2, KP_, p_ppre, G4_, 1);

    persist_kernel<<<nsm, 256, SMEM_FLOATS_*4>>>(input_q, mask_q, mask_p,
                                                 b_att, w_att, out, nsm);
}